// round 6
// baseline (speedup 1.0000x reference)
#include <cuda_runtime.h>
#include <math.h>

#define N_ATOMS 4096
#define NRBF    16
#define NHID    64
#define TPB     256
#define WPB     (TPB / 32)            // 8 warps (atoms) per block
#define NBLK    (N_ATOMS / WPB)       // 512 blocks

// ---- scratch (no allocations allowed) ----
__device__ float4 g_pos4[N_ATOMS];    // packed positions for LDG.128
__device__ float  g_atomic_e[N_ATOMS];

// 1/(2*eta^2), eta = 0.5*(5.0-0.5)/16 = 9/64 -> A = 2048/81
#define RBF_A        25.28395061728395f
#define PI_OVER_CUT  0.6283185307179586f   // pi / 5.0
#define CUT_SQ       25.0f

// ============================================================
// Kernel 0: pack positions (float3 strided -> float4 aligned)
// ============================================================
__global__ __launch_bounds__(256)
void prep_kernel(const float* __restrict__ pos)
{
    int i = blockIdx.x * 256 + threadIdx.x;
    if (i < N_ATOMS)
        g_pos4[i] = make_float4(pos[3 * i], pos[3 * i + 1], pos[3 * i + 2], 0.0f);
}

// ============================================================
// Dense RBF batch: every lane holds one accepted sq (or 1e8 sentinel)
// ============================================================
__device__ __forceinline__ void rbf_batch(float sq, const float* __restrict__ c,
                                          float* __restrict__ f)
{
    float d = sqrtf(sq);
    float w = 0.5f + 0.5f * __cosf(d * PI_OVER_CUT);
    #pragma unroll
    for (int k = 0; k < NRBF; k++) {
        float tt = d - c[k];
        float g  = __expf(-RBF_A * tt * tt);   // sentinel d=1e4 -> g underflows to 0
        f[k] = fmaf(w, g, f[k]);
    }
}

__device__ __forceinline__ float silu_f(float a)
{
    return a / (1.0f + __expf(-a));
}

// ============================================================
// Kernel 1: fused pairwise-RBF features + per-atom MLP.
// One warp per atom i. Lanes scan 32 j's per iteration; accepted
// pairs are compacted into a per-warp queue (ballot + prefix, j-order
// -> deterministic) and processed in dense 32-wide batches.
// ============================================================
__global__ __launch_bounds__(TPB)
void fused_kernel(const float* __restrict__ centers,
                  const float* __restrict__ W1, const float* __restrict__ b1,
                  const float* __restrict__ W2, const float* __restrict__ b2,
                  const float* __restrict__ W3, const float* __restrict__ b3)
{
    __shared__ float s_buf[WPB][64];     // accepted-sq queue per warp
    __shared__ float s_h1[WPB][NHID];    // hidden layer 1 activations

    const int warp = threadIdx.x >> 5;
    const int lane = threadIdx.x & 31;
    const int i    = blockIdx.x * WPB + warp;

    const float4 pi = g_pos4[i];

    float c[NRBF];
    #pragma unroll
    for (int k = 0; k < NRBF; k++) c[k] = __ldg(&centers[k]);

    float f[NRBF];
    #pragma unroll
    for (int k = 0; k < NRBF; k++) f[k] = 0.0f;

    const unsigned lt_mask = (1u << lane) - 1u;
    int cnt = 0;

    #pragma unroll 4
    for (int jb = 0; jb < N_ATOMS; jb += 32) {
        float4 pj = g_pos4[jb + lane];
        float dx = pi.x - pj.x;
        float dy = pi.y - pj.y;
        float dz = pi.z - pj.z;
        float sq = fmaf(dx, dx, fmaf(dy, dy, dz * dz));
        bool ok  = (sq > 0.0f) && (sq < CUT_SQ);   // excludes self (sq==0)
        unsigned m = __ballot_sync(0xffffffffu, ok);
        if (ok)
            s_buf[warp][cnt + __popc(m & lt_mask)] = sq;
        cnt += __popc(m);
        if (cnt >= 32) {                 // rare: ~30 accepts / 128 iters
            cnt -= 32;
            __syncwarp();
            float sqv = s_buf[warp][cnt + lane];
            __syncwarp();
            rbf_batch(sqv, c, f);
        }
    }
    // tail batch (cnt in [0,31])
    __syncwarp();
    {
        float sqv = (lane < cnt) ? s_buf[warp][lane] : 1e8f;  // sentinel -> 0 contribution
        if (cnt > 0)
            rbf_batch(sqv, c, f);
    }

    // butterfly-reduce features: afterwards EVERY lane holds the full feats
    #pragma unroll
    for (int off = 16; off > 0; off >>= 1) {
        #pragma unroll
        for (int k = 0; k < NRBF; k++)
            f[k] += __shfl_xor_sync(0xffffffffu, f[k], off);
    }

    // ---- MLP, 2 hidden units per lane ----
    // layer 1: 16 -> 64
    const int t0 = lane, t1 = lane + 32;
    float a0 = __ldg(&b1[t0]);
    float a1 = __ldg(&b1[t1]);
    #pragma unroll
    for (int k = 0; k < NRBF; k++) {
        a0 = fmaf(f[k], __ldg(&W1[k * NHID + t0]), a0);
        a1 = fmaf(f[k], __ldg(&W1[k * NHID + t1]), a1);
    }
    s_h1[warp][t0] = silu_f(a0);
    s_h1[warp][t1] = silu_f(a1);
    __syncwarp();

    // layer 2: 64 -> 64 (broadcast LDS.128 of h1)
    float a2 = __ldg(&b2[t0]);
    float a3 = __ldg(&b2[t1]);
    #pragma unroll
    for (int u = 0; u < NHID; u += 4) {
        float4 hv = *reinterpret_cast<const float4*>(&s_h1[warp][u]);
        a2 = fmaf(hv.x, __ldg(&W2[(u + 0) * NHID + t0]), a2);
        a2 = fmaf(hv.y, __ldg(&W2[(u + 1) * NHID + t0]), a2);
        a2 = fmaf(hv.z, __ldg(&W2[(u + 2) * NHID + t0]), a2);
        a2 = fmaf(hv.w, __ldg(&W2[(u + 3) * NHID + t0]), a2);
        a3 = fmaf(hv.x, __ldg(&W2[(u + 0) * NHID + t1]), a3);
        a3 = fmaf(hv.y, __ldg(&W2[(u + 1) * NHID + t1]), a3);
        a3 = fmaf(hv.z, __ldg(&W2[(u + 2) * NHID + t1]), a3);
        a3 = fmaf(hv.w, __ldg(&W2[(u + 3) * NHID + t1]), a3);
    }

    // layer 3 partials + warp reduce
    float v = silu_f(a2) * __ldg(&W3[t0]) + silu_f(a3) * __ldg(&W3[t1]);
    #pragma unroll
    for (int off = 16; off > 0; off >>= 1)
        v += __shfl_down_sync(0xffffffffu, v, off);
    if (lane == 0)
        g_atomic_e[i] = v + __ldg(&b3[0]);
}

// ============================================================
// Kernel 2: deterministic sum of per-atom energies
// ============================================================
__global__ __launch_bounds__(1024)
void reduce_kernel(float* __restrict__ out)
{
    __shared__ float sh[1024];
    const int t = threadIdx.x;
    float v = 0.0f;
    #pragma unroll
    for (int i = t; i < N_ATOMS; i += 1024)
        v += g_atomic_e[i];
    sh[t] = v;
    __syncthreads();
    #pragma unroll
    for (int s = 512; s > 0; s >>= 1) {
        if (t < s) sh[t] += sh[t + s];
        __syncthreads();
    }
    if (t == 0) out[0] = sh[0];
}

// ============================================================
extern "C" void kernel_launch(void* const* d_in, const int* in_sizes, int n_in,
                              void* d_out, int out_size)
{
    const float* pos     = (const float*)d_in[0];
    const float* centers = (const float*)d_in[1];
    const float* W1      = (const float*)d_in[2];
    const float* b1      = (const float*)d_in[3];
    const float* W2      = (const float*)d_in[4];
    const float* b2      = (const float*)d_in[5];
    const float* W3      = (const float*)d_in[6];
    const float* b3      = (const float*)d_in[7];

    prep_kernel<<<(N_ATOMS + 255) / 256, 256>>>(pos);
    fused_kernel<<<NBLK, TPB>>>(centers, W1, b1, W2, b2, W3, b3);
    reduce_kernel<<<1, 1024>>>((float*)d_out);
}

// round 7
// speedup vs baseline: 1.8058x; 1.8058x over previous
#include <cuda_runtime.h>
#include <math.h>

#define N_ATOMS  4096
#define NRBF     16
#define NHID     64

#define NCELL1   8                    // cells per axis (BOX/CUTOFF = 40/5)
#define NCELLS   (NCELL1*NCELL1*NCELL1)  // 512
#define CELL_CAP 64                   // mean occupancy ~8; 64 is ~8 sigma
#define CAND_CAP 512                  // 27 cells * mean 8 = ~216; huge margin
#define INV_CELL 0.2f                 // 1 / 5.0

// ---- scratch (no allocations allowed) ----
__device__ float4 g_pos4[N_ATOMS];
__device__ int    g_cellid[N_ATOMS];
__device__ int    g_cell_cnt[NCELLS];
__device__ int    g_cell_atoms[NCELLS * CELL_CAP];
__device__ float  g_atomic_e[N_ATOMS];

// 1/(2*eta^2), eta = 0.5*(5.0-0.5)/16 = 9/64 -> A = 2048/81
#define RBF_A        25.28395061728395f
#define PI_OVER_CUT  0.6283185307179586f   // pi / 5.0
#define CUT_SQ       25.0f

// ============================================================
// Kernel 0: pack positions + cell ids
// ============================================================
__global__ __launch_bounds__(128)
void prep_kernel(const float* __restrict__ pos)
{
    int i = blockIdx.x * 128 + threadIdx.x;
    if (i >= N_ATOMS) return;
    float x = pos[3 * i], y = pos[3 * i + 1], z = pos[3 * i + 2];
    g_pos4[i] = make_float4(x, y, z, 0.0f);
    int cx = min(NCELL1 - 1, max(0, (int)(x * INV_CELL)));
    int cy = min(NCELL1 - 1, max(0, (int)(y * INV_CELL)));
    int cz = min(NCELL1 - 1, max(0, (int)(z * INV_CELL)));
    g_cellid[i] = (cz * NCELL1 + cy) * NCELL1 + cx;
}

// ============================================================
// Kernel 1: build per-cell atom lists (deterministic, index order)
// one warp per cell; 64 blocks x 8 warps = 512 warps
// ============================================================
__global__ __launch_bounds__(256)
void fill_kernel()
{
    __shared__ int s_ids[N_ATOMS];   // 16 KB

    const int warp = threadIdx.x >> 5;
    const int lane = threadIdx.x & 31;
    const int cell = blockIdx.x * 8 + warp;

    for (int t = threadIdx.x; t < N_ATOMS; t += 256)
        s_ids[t] = g_cellid[t];
    __syncthreads();

    const unsigned lt = (1u << lane) - 1u;
    int cnt = 0;
    int* dst = &g_cell_atoms[cell * CELL_CAP];

    #pragma unroll 4
    for (int b = 0; b < N_ATOMS; b += 32) {
        bool m = (s_ids[b + lane] == cell);
        unsigned bal = __ballot_sync(0xffffffffu, m);
        if (m) {
            int ofs = cnt + __popc(bal & lt);
            if (ofs < CELL_CAP) dst[ofs] = b + lane;
        }
        cnt += __popc(bal);
    }
    if (lane == 0) g_cell_cnt[cell] = min(cnt, CELL_CAP);
}

// ============================================================
__device__ __forceinline__ float silu_f(float a)
{
    return a / (1.0f + __expf(-a));
}

// ============================================================
// Kernel 2: gather RBF features from 27 neighbor cells + fused MLP
// one warp per atom; 512 blocks x 8 warps
// ============================================================
__global__ __launch_bounds__(256)
void gather_kernel(const float* __restrict__ centers,
                   const float* __restrict__ W1, const float* __restrict__ b1,
                   const float* __restrict__ W2, const float* __restrict__ b2,
                   const float* __restrict__ W3, const float* __restrict__ b3)
{
    __shared__ int   s_cand[8][CAND_CAP];  // 16 KB
    __shared__ float s_h1[8][NHID];        // 2 KB

    const int warp = threadIdx.x >> 5;
    const int lane = threadIdx.x & 31;
    const int i    = blockIdx.x * 8 + warp;

    const float4 pi = g_pos4[i];
    const int cx = min(NCELL1 - 1, max(0, (int)(pi.x * INV_CELL)));
    const int cy = min(NCELL1 - 1, max(0, (int)(pi.y * INV_CELL)));
    const int cz = min(NCELL1 - 1, max(0, (int)(pi.z * INV_CELL)));

    // ---- build candidate list from 27 neighbor cells ----
    int nc = 0;
    for (int dz = -1; dz <= 1; dz++) {
        int z = cz + dz; if (z < 0 || z >= NCELL1) continue;
        for (int dy = -1; dy <= 1; dy++) {
            int y = cy + dy; if (y < 0 || y >= NCELL1) continue;
            for (int dx = -1; dx <= 1; dx++) {
                int x = cx + dx; if (x < 0 || x >= NCELL1) continue;
                int c   = (z * NCELL1 + y) * NCELL1 + x;
                int cnt = g_cell_cnt[c];
                cnt = min(cnt, CAND_CAP - nc);
                const int* ca = &g_cell_atoms[c * CELL_CAP];
                for (int b = 0; b < cnt; b += 32)
                    if (lane < cnt - b)
                        s_cand[warp][nc + b + lane] = ca[b + lane];
                nc += cnt;
            }
        }
    }
    __syncwarp();

    // ---- dense RBF over candidates (masked, branch-free hot loop) ----
    float c[NRBF];
    #pragma unroll
    for (int k = 0; k < NRBF; k++) c[k] = __ldg(&centers[k]);

    float f[NRBF];
    #pragma unroll
    for (int k = 0; k < NRBF; k++) f[k] = 0.0f;

    const int iters = (nc + 31) >> 5;
    for (int it = 0; it < iters; it++) {
        int idx = (it << 5) + lane;
        int j   = (idx < nc) ? s_cand[warp][idx] : i;   // pad with self -> sq==0 -> masked
        float4 pj = g_pos4[j];
        float dx = pi.x - pj.x;
        float dy = pi.y - pj.y;
        float dz = pi.z - pj.z;
        float sq = fmaf(dx, dx, fmaf(dy, dy, dz * dz));
        bool ok  = (sq > 0.0f) && (sq < CUT_SQ);        // excludes self exactly
        float d  = sqrtf(sq);
        float w  = ok ? (0.5f + 0.5f * __cosf(d * PI_OVER_CUT)) : 0.0f;
        #pragma unroll
        for (int k = 0; k < NRBF; k++) {
            float tt = d - c[k];
            float g  = __expf(-RBF_A * tt * tt);
            f[k] = fmaf(w, g, f[k]);
        }
    }

    // butterfly-reduce features: every lane ends with the full vector
    #pragma unroll
    for (int off = 16; off > 0; off >>= 1) {
        #pragma unroll
        for (int k = 0; k < NRBF; k++)
            f[k] += __shfl_xor_sync(0xffffffffu, f[k], off);
    }

    // ---- MLP, 2 hidden units per lane (verified in R6) ----
    const int t0 = lane, t1 = lane + 32;
    float a0 = __ldg(&b1[t0]);
    float a1 = __ldg(&b1[t1]);
    #pragma unroll
    for (int k = 0; k < NRBF; k++) {
        a0 = fmaf(f[k], __ldg(&W1[k * NHID + t0]), a0);
        a1 = fmaf(f[k], __ldg(&W1[k * NHID + t1]), a1);
    }
    s_h1[warp][t0] = silu_f(a0);
    s_h1[warp][t1] = silu_f(a1);
    __syncwarp();

    float a2 = __ldg(&b2[t0]);
    float a3 = __ldg(&b2[t1]);
    #pragma unroll
    for (int u = 0; u < NHID; u += 4) {
        float4 hv = *reinterpret_cast<const float4*>(&s_h1[warp][u]);
        a2 = fmaf(hv.x, __ldg(&W2[(u + 0) * NHID + t0]), a2);
        a2 = fmaf(hv.y, __ldg(&W2[(u + 1) * NHID + t0]), a2);
        a2 = fmaf(hv.z, __ldg(&W2[(u + 2) * NHID + t0]), a2);
        a2 = fmaf(hv.w, __ldg(&W2[(u + 3) * NHID + t0]), a2);
        a3 = fmaf(hv.x, __ldg(&W2[(u + 0) * NHID + t1]), a3);
        a3 = fmaf(hv.y, __ldg(&W2[(u + 1) * NHID + t1]), a3);
        a3 = fmaf(hv.z, __ldg(&W2[(u + 2) * NHID + t1]), a3);
        a3 = fmaf(hv.w, __ldg(&W2[(u + 3) * NHID + t1]), a3);
    }

    float v = silu_f(a2) * __ldg(&W3[t0]) + silu_f(a3) * __ldg(&W3[t1]);
    #pragma unroll
    for (int off = 16; off > 0; off >>= 1)
        v += __shfl_down_sync(0xffffffffu, v, off);
    if (lane == 0)
        g_atomic_e[i] = v + __ldg(&b3[0]);
}

// ============================================================
// Kernel 3: deterministic sum of per-atom energies
// ============================================================
__global__ __launch_bounds__(1024)
void reduce_kernel(float* __restrict__ out)
{
    __shared__ float sh[1024];
    const int t = threadIdx.x;
    float v = 0.0f;
    #pragma unroll
    for (int i = t; i < N_ATOMS; i += 1024)
        v += g_atomic_e[i];
    sh[t] = v;
    __syncthreads();
    #pragma unroll
    for (int s = 512; s > 0; s >>= 1) {
        if (t < s) sh[t] += sh[t + s];
        __syncthreads();
    }
    if (t == 0) out[0] = sh[0];
}

// ============================================================
extern "C" void kernel_launch(void* const* d_in, const int* in_sizes, int n_in,
                              void* d_out, int out_size)
{
    const float* pos     = (const float*)d_in[0];
    const float* centers = (const float*)d_in[1];
    const float* W1      = (const float*)d_in[2];
    const float* b1      = (const float*)d_in[3];
    const float* W2      = (const float*)d_in[4];
    const float* b2      = (const float*)d_in[5];
    const float* W3      = (const float*)d_in[6];
    const float* b3      = (const float*)d_in[7];

    prep_kernel<<<N_ATOMS / 128, 128>>>(pos);
    fill_kernel<<<NCELLS / 8, 256>>>();
    gather_kernel<<<N_ATOMS / 8, 256>>>(centers, W1, b1, W2, b2, W3, b3);
    reduce_kernel<<<1, 1024>>>((float*)d_out);
}

// round 8
// speedup vs baseline: 2.2042x; 1.2206x over previous
#include <cuda_runtime.h>
#include <math.h>

#define N_ATOMS  4096
#define NRBF     16
#define NHID     64

#define NCELL1   8                       // cells per axis (BOX/CUTOFF = 40/5)
#define NCELLS   (NCELL1*NCELL1*NCELL1)  // 512
#define CELL_CAP 64                      // mean occupancy ~8
#define CAND_CAP 384                     // 27 cells * ~8 = ~216 expected
#define ACC_CAP  128                     // accepted neighbors: mean ~33
#define INV_CELL 0.2f                    // 1 / 5.0

// ---- scratch (no allocations allowed) ----
__device__ float4 g_pos4[N_ATOMS];
__device__ int    g_cell_cnt[NCELLS];
__device__ int    g_cell_atoms[NCELLS * CELL_CAP];
__device__ float  g_block_e[N_ATOMS / 8];   // 512 per-block energy partials
__device__ int    g_done;                   // last-block ticket (reset in build)

// 1/(2*eta^2), eta = 0.5*(5.0-0.5)/16 = 9/64 -> A = 2048/81
#define RBF_A        25.28395061728395f
#define PI_OVER_CUT  0.6283185307179586f    // pi / 5.0
#define CUT_SQ       25.0f

__device__ __forceinline__ int cell_of(float x, float y, float z)
{
    int cx = min(NCELL1 - 1, max(0, (int)(x * INV_CELL)));
    int cy = min(NCELL1 - 1, max(0, (int)(y * INV_CELL)));
    int cz = min(NCELL1 - 1, max(0, (int)(z * INV_CELL)));
    return (cz * NCELL1 + cy) * NCELL1 + cx;
}

// ============================================================
// Kernel 1: pack positions + build per-cell atom lists.
// 64 blocks x 256 threads; each block scans all atoms (cellids
// recomputed locally), owns 8 cells (warp per cell) and writes
// its own 64-atom slice of g_pos4. Deterministic (index order).
// ============================================================
__global__ __launch_bounds__(256)
void build_kernel(const float* __restrict__ pos)
{
    __shared__ int s_ids[N_ATOMS];   // 16 KB

    const int tid  = threadIdx.x;
    const int warp = tid >> 5;
    const int lane = tid & 31;

    if (blockIdx.x == 0 && tid == 0) g_done = 0;   // reset ticket for this replay

    // cellids for all atoms (each block computes all -> no inter-block dep)
    for (int a = tid; a < N_ATOMS; a += 256) {
        float x = pos[3 * a], y = pos[3 * a + 1], z = pos[3 * a + 2];
        s_ids[a] = cell_of(x, y, z);
    }
    // this block's 64-atom slice of packed positions
    if (tid < 64) {
        int a = blockIdx.x * 64 + tid;
        g_pos4[a] = make_float4(pos[3 * a], pos[3 * a + 1], pos[3 * a + 2], 0.0f);
    }
    __syncthreads();

    // warp-per-cell compaction scan (index order -> deterministic)
    const int cell = blockIdx.x * 8 + warp;
    const unsigned lt = (1u << lane) - 1u;
    int cnt = 0;
    int* dst = &g_cell_atoms[cell * CELL_CAP];

    #pragma unroll 4
    for (int b = 0; b < N_ATOMS; b += 32) {
        bool m = (s_ids[b + lane] == cell);
        unsigned bal = __ballot_sync(0xffffffffu, m);
        if (m) {
            int ofs = cnt + __popc(bal & lt);
            if (ofs < CELL_CAP) dst[ofs] = b + lane;
        }
        cnt += __popc(bal);
    }
    if (lane == 0) g_cell_cnt[cell] = min(cnt, CELL_CAP);
}

// ============================================================
__device__ __forceinline__ float silu_f(float a)
{
    return a / (1.0f + __expf(-a));
}

__device__ __forceinline__ void rbf_batch(float sq, const float* __restrict__ c,
                                          float* __restrict__ f)
{
    float d = sqrtf(sq);                         // sentinel sq=1e8 -> d=1e4
    float w = 0.5f + 0.5f * __cosf(d * PI_OVER_CUT);
    #pragma unroll
    for (int k = 0; k < NRBF; k++) {
        float tt = d - c[k];
        float g  = __expf(-RBF_A * tt * tt);     // sentinel -> underflow to 0
        f[k] = fmaf(w, g, f[k]);
    }
}

// ============================================================
// Kernel 2: candidates from 27 neighbor cells -> filter+compact
// -> dense RBF -> fused MLP -> block partial -> last-block sum.
// One warp per atom; 512 blocks x 256 threads.
// ============================================================
__global__ __launch_bounds__(256)
void gather_kernel(const float* __restrict__ centers,
                   const float* __restrict__ W1, const float* __restrict__ b1,
                   const float* __restrict__ W2, const float* __restrict__ b2,
                   const float* __restrict__ W3, const float* __restrict__ b3,
                   float* __restrict__ out)
{
    __shared__ int   s_cand[8][CAND_CAP];   // 12 KB candidate indices
    __shared__ float s_acc[8][ACC_CAP];     //  4 KB accepted sq values
    __shared__ float s_h1[8][NHID];         //  2 KB hidden activations
    __shared__ float s_e[8];                // warp energies
    __shared__ int   s_last;
    __shared__ float s_red[256];

    const int tid  = threadIdx.x;
    const int warp = tid >> 5;
    const int lane = tid & 31;
    const int i    = blockIdx.x * 8 + warp;
    const unsigned FULL = 0xffffffffu;
    const unsigned lt   = (1u << lane) - 1u;

    const float4 pi = g_pos4[i];
    const int cx = min(NCELL1 - 1, max(0, (int)(pi.x * INV_CELL)));
    const int cy = min(NCELL1 - 1, max(0, (int)(pi.y * INV_CELL)));
    const int cz = min(NCELL1 - 1, max(0, (int)(pi.z * INV_CELL)));

    // ---- parallel neighbor-cell census: lane l -> cell l of the 3x3x3 ----
    int cellc = 0, cntc = 0;
    if (lane < 27) {
        int dz = lane / 9 - 1, r = lane % 9;
        int dy = r / 3 - 1,    dx = r % 3 - 1;
        int x = cx + dx, y = cy + dy, z = cz + dz;
        if (x >= 0 && x < NCELL1 && y >= 0 && y < NCELL1 && z >= 0 && z < NCELL1) {
            cellc = (z * NCELL1 + y) * NCELL1 + x;
            cntc  = g_cell_cnt[cellc];
        }
    }
    // inclusive prefix sum of counts over lanes
    int pre = cntc;
    #pragma unroll
    for (int d = 1; d < 32; d <<= 1) {
        int n = __shfl_up_sync(FULL, pre, d);
        if (lane >= d) pre += n;
    }
    int offc = pre - cntc;                       // exclusive offset for my cell
    int nc   = __shfl_sync(FULL, pre, 31);       // total candidates
    nc = min(nc, CAND_CAP);

    // ---- copy candidate lists (uniform counts via shfl; no serial LDG dep) ----
    for (int cI = 0; cI < 27; cI++) {
        int cnt_b  = __shfl_sync(FULL, cntc,  cI);
        int off_b  = __shfl_sync(FULL, offc,  cI);
        int cell_b = __shfl_sync(FULL, cellc, cI);
        if (cnt_b == 0) continue;                        // uniform branch
        cnt_b = min(cnt_b, CAND_CAP - off_b);
        const int* ca = &g_cell_atoms[cell_b * CELL_CAP];
        if (lane < cnt_b)      s_cand[warp][off_b + lane]      = ca[lane];
        if (lane + 32 < cnt_b) s_cand[warp][off_b + 32 + lane] = ca[lane + 32];
    }
    __syncwarp();

    // ---- filter pass: compact accepted sq (candidate order -> deterministic) ----
    int acc = 0;
    const int iters = (nc + 31) >> 5;
    for (int it = 0; it < iters; it++) {
        int idx = (it << 5) + lane;
        int j   = (idx < nc) ? s_cand[warp][idx] : i;    // self-pad -> sq==0 -> rejected
        float4 pj = g_pos4[j];
        float dx = pi.x - pj.x;
        float dy = pi.y - pj.y;
        float dz = pi.z - pj.z;
        float sq = fmaf(dx, dx, fmaf(dy, dy, dz * dz));
        bool ok  = (sq > 0.0f) && (sq < CUT_SQ);         // excludes self exactly
        unsigned m = __ballot_sync(FULL, ok);
        if (ok) {
            int ofs = acc + __popc(m & lt);
            if (ofs < ACC_CAP) s_acc[warp][ofs] = sq;
        }
        acc += __popc(m);
    }
    acc = min(acc, ACC_CAP);
    __syncwarp();

    // ---- dense RBF over accepted pairs only (~2 batches typical) ----
    float c[NRBF];
    #pragma unroll
    for (int k = 0; k < NRBF; k++) c[k] = __ldg(&centers[k]);

    float f[NRBF];
    #pragma unroll
    for (int k = 0; k < NRBF; k++) f[k] = 0.0f;

    for (int b = 0; b < acc; b += 32) {
        float sqv = (b + lane < acc) ? s_acc[warp][b + lane] : 1e8f;
        rbf_batch(sqv, c, f);
    }

    // butterfly-reduce features: every lane ends with the full vector
    #pragma unroll
    for (int off = 16; off > 0; off >>= 1) {
        #pragma unroll
        for (int k = 0; k < NRBF; k++)
            f[k] += __shfl_xor_sync(FULL, f[k], off);
    }

    // ---- MLP, 2 hidden units per lane ----
    const int t0 = lane, t1 = lane + 32;
    float a0 = __ldg(&b1[t0]);
    float a1 = __ldg(&b1[t1]);
    #pragma unroll
    for (int k = 0; k < NRBF; k++) {
        a0 = fmaf(f[k], __ldg(&W1[k * NHID + t0]), a0);
        a1 = fmaf(f[k], __ldg(&W1[k * NHID + t1]), a1);
    }
    s_h1[warp][t0] = silu_f(a0);
    s_h1[warp][t1] = silu_f(a1);
    __syncwarp();

    float a2 = __ldg(&b2[t0]);
    float a3 = __ldg(&b2[t1]);
    #pragma unroll
    for (int u = 0; u < NHID; u += 4) {
        float4 hv = *reinterpret_cast<const float4*>(&s_h1[warp][u]);
        a2 = fmaf(hv.x, __ldg(&W2[(u + 0) * NHID + t0]), a2);
        a2 = fmaf(hv.y, __ldg(&W2[(u + 1) * NHID + t0]), a2);
        a2 = fmaf(hv.z, __ldg(&W2[(u + 2) * NHID + t0]), a2);
        a2 = fmaf(hv.w, __ldg(&W2[(u + 3) * NHID + t0]), a2);
        a3 = fmaf(hv.x, __ldg(&W2[(u + 0) * NHID + t1]), a3);
        a3 = fmaf(hv.y, __ldg(&W2[(u + 1) * NHID + t1]), a3);
        a3 = fmaf(hv.z, __ldg(&W2[(u + 2) * NHID + t1]), a3);
        a3 = fmaf(hv.w, __ldg(&W2[(u + 3) * NHID + t1]), a3);
    }

    float v = silu_f(a2) * __ldg(&W3[t0]) + silu_f(a3) * __ldg(&W3[t1]);
    #pragma unroll
    for (int off = 16; off > 0; off >>= 1)
        v += __shfl_down_sync(FULL, v, off);
    if (lane == 0) s_e[warp] = v + __ldg(&b3[0]);
    __syncthreads();

    // ---- block partial + last-block deterministic reduction ----
    if (tid == 0) {
        float be = 0.0f;
        #pragma unroll
        for (int w = 0; w < 8; w++) be += s_e[w];
        g_block_e[blockIdx.x] = be;
        __threadfence();
        int t = atomicAdd(&g_done, 1);
        s_last = (t == gridDim.x - 1);
    }
    __syncthreads();

    if (s_last) {
        float v2 = g_block_e[tid] + g_block_e[tid + 256];  // fixed order
        s_red[tid] = v2;
        __syncthreads();
        #pragma unroll
        for (int s = 128; s > 0; s >>= 1) {
            if (tid < s) s_red[tid] += s_red[tid + s];
            __syncthreads();
        }
        if (tid == 0) out[0] = s_red[0];
    }
}

// ============================================================
extern "C" void kernel_launch(void* const* d_in, const int* in_sizes, int n_in,
                              void* d_out, int out_size)
{
    const float* pos     = (const float*)d_in[0];
    const float* centers = (const float*)d_in[1];
    const float* W1      = (const float*)d_in[2];
    const float* b1      = (const float*)d_in[3];
    const float* W2      = (const float*)d_in[4];
    const float* b2      = (const float*)d_in[5];
    const float* W3      = (const float*)d_in[6];
    const float* b3      = (const float*)d_in[7];

    build_kernel<<<NCELLS / 8, 256>>>(pos);
    gather_kernel<<<N_ATOMS / 8, 256>>>(centers, W1, b1, W2, b2, W3, b3,
                                        (float*)d_out);
}